// round 1
// baseline (speedup 1.0000x reference)
#include <cuda_runtime.h>
#include <cuda_bf16.h>
#include <mma.h>

using namespace nvcuda;

#define BB 32
#define SS 128
#define UU 256
#define HH 128
#define VV 30001

// scratch for RNN outputs (outs transposed to [B,S,H] row-major), 2 MB
__device__ float g_outs[BB * SS * HH];

// ---------------------------------------------------------------------------
// RNN kernel: one CTA per batch (32 CTAs), 384 threads.
//   threads [0,256)  : hold one column of W_ru in registers, compute ru
//   threads [256,384): hold one column of W_c  in registers, compute c, h_new
// Full per-batch state lives in shared memory (128 KB).
// ---------------------------------------------------------------------------
__global__ __launch_bounds__(384, 1)
void rnn_kernel(const int* __restrict__ users, const int* __restrict__ items,
                const float* __restrict__ h0,
                const float* __restrict__ P_ru, const float* __restrict__ W_ru,
                const float* __restrict__ b_ru,
                const float* __restrict__ P_c, const float* __restrict__ W_c,
                const float* __restrict__ b_c)
{
    extern __shared__ float sm[];
    float* state_s = sm;                      // UU*HH floats
    float* rh_s    = sm + UU * HH;            // HH
    float* z_s     = rh_s + HH;               // HH
    int*   users_s = (int*)(z_s + HH);        // SS
    int*   items_s = users_s + SS;            // SS

    const int b   = blockIdx.x;
    const int tid = threadIdx.x;

    // preload index sequences
    for (int t = tid; t < SS; t += blockDim.x) {
        users_s[t] = users[b * SS + t];
        items_s[t] = items[b * SS + t];
    }
    // load initial state h0[b] into smem
    {
        const float4* src = (const float4*)(h0 + (size_t)b * UU * HH);
        float4* dst = (float4*)state_s;
        for (int i = tid; i < UU * HH / 4; i += blockDim.x) dst[i] = src[i];
    }

    // weight column -> registers
    float wreg[HH];
    float breg;
    if (tid < 2 * HH) {
        #pragma unroll
        for (int k = 0; k < HH; k++) wreg[k] = W_ru[k * (2 * HH) + tid];
        breg = b_ru[tid];
    } else {
        const int j = tid - 2 * HH;
        #pragma unroll
        for (int k = 0; k < HH; k++) wreg[k] = W_c[k * HH + j];
        breg = b_c[j];
    }
    __syncthreads();

    for (int t = 0; t < SS; t++) {
        const int u  = users_s[t];
        const int it = items_s[t];

        float p2 = 0.f;
        if (tid >= 2 * HH) {
            // prefetch P_c row early (latency hidden behind phase 1)
            p2 = P_c[(size_t)it * HH + (tid - 2 * HH)];
        } else {
            float p = P_ru[(size_t)it * (2 * HH) + tid];
            const float* hs = state_s + u * HH;
            float a0 = 0.f, a1 = 0.f, a2 = 0.f, a3 = 0.f;
            #pragma unroll
            for (int k = 0; k < HH; k += 4) {
                float4 h4 = *(const float4*)(hs + k);
                a0 += h4.x * wreg[k];
                a1 += h4.y * wreg[k + 1];
                a2 += h4.z * wreg[k + 2];
                a3 += h4.w * wreg[k + 3];
            }
            float x = p + breg + (a0 + a1) + (a2 + a3);
            float sgm = 1.f / (1.f + __expf(-x));
            if (tid < HH) rh_s[tid] = sgm * hs[tid];   // r * h_prev
            else          z_s[tid - HH] = sgm;         // z
        }
        __syncthreads();

        if (tid >= 2 * HH) {
            const int j = tid - 2 * HH;
            float a0 = 0.f, a1 = 0.f, a2 = 0.f, a3 = 0.f;
            #pragma unroll
            for (int k = 0; k < HH; k += 4) {
                float4 r4 = *(const float4*)(rh_s + k);
                a0 += r4.x * wreg[k];
                a1 += r4.y * wreg[k + 1];
                a2 += r4.z * wreg[k + 2];
                a3 += r4.w * wreg[k + 3];
            }
            float x = p2 + breg + (a0 + a1) + (a2 + a3);
            float c = tanhf(x);
            float h_old = state_s[u * HH + j];
            float z = z_s[j];
            float hn = z * h_old + (1.f - z) * c;
            state_s[u * HH + j] = hn;
            g_outs[((size_t)b * SS + t) * HH + j] = hn;
        }
        __syncthreads();
    }
}

// ---------------------------------------------------------------------------
// Logits GEMM: out[4096, 30001] = g_outs[4096,128] @ ws[128,30001]
// WMMA tf32 (m16n16k8), CTA tile 128x128, full K=128 staged in smem.
// 8 warps, warp tile 32x64.
// ---------------------------------------------------------------------------
#define GTM 128
#define GTN 128
#define LDA 132
#define LDB 132

__global__ __launch_bounds__(256, 1)
void gemm_kernel(const float* __restrict__ ws, float* __restrict__ out)
{
    extern __shared__ float sm[];
    float* As = sm;                 // [128][LDA]
    float* Bs = sm + GTM * LDA;     // [128][LDB]

    const int tid = threadIdx.x;
    const int n0 = blockIdx.x * GTN;
    const int m0 = blockIdx.y * GTM;

    // A tile: 128 rows x 128 k from g_outs (ld = HH), vectorized
    {
        const float4* src = (const float4*)(g_outs + (size_t)m0 * HH);
        for (int i = tid; i < GTM * HH / 4; i += 256) {
            int r = i >> 5;          // 32 float4 per row
            int c = i & 31;
            *(float4*)(As + r * LDA + c * 4) = src[r * 32 + c];
        }
    }
    // B tile: 128 k x 128 n from ws (ld = VV, odd -> scalar, bounds-checked)
    {
        for (int i = tid; i < HH * GTN; i += 256) {
            int k = i >> 7;
            int c = i & 127;
            int n = n0 + c;
            Bs[k * LDB + c] = (n < VV) ? ws[(size_t)k * VV + n] : 0.f;
        }
    }
    __syncthreads();

    const int wid = tid >> 5;
    const int wm = wid & 3;          // 4 warps over M
    const int wn = wid >> 2;         // 2 warps over N

    wmma::fragment<wmma::accumulator, 16, 16, 8, float> acc[2][4];
    #pragma unroll
    for (int i = 0; i < 2; i++)
        #pragma unroll
        for (int j = 0; j < 4; j++)
            wmma::fill_fragment(acc[i][j], 0.f);

    #pragma unroll
    for (int k = 0; k < HH; k += 8) {
        wmma::fragment<wmma::matrix_a, 16, 16, 8, wmma::precision::tf32, wmma::row_major> afr[2];
        wmma::fragment<wmma::matrix_b, 16, 16, 8, wmma::precision::tf32, wmma::row_major> bfr[4];
        #pragma unroll
        for (int i = 0; i < 2; i++) {
            wmma::load_matrix_sync(afr[i], As + (wm * 32 + i * 16) * LDA + k, LDA);
            #pragma unroll
            for (int e = 0; e < afr[i].num_elements; e++)
                afr[i].x[e] = wmma::__float_to_tf32(afr[i].x[e]);
        }
        #pragma unroll
        for (int j = 0; j < 4; j++) {
            wmma::load_matrix_sync(bfr[j], Bs + k * LDB + wn * 64 + j * 16, LDB);
            #pragma unroll
            for (int e = 0; e < bfr[j].num_elements; e++)
                bfr[j].x[e] = wmma::__float_to_tf32(bfr[j].x[e]);
        }
        #pragma unroll
        for (int i = 0; i < 2; i++)
            #pragma unroll
            for (int j = 0; j < 4; j++)
                wmma::mma_sync(acc[i][j], afr[i], bfr[j], acc[i][j]);
    }

    // stage C in smem (reuse As/Bs region), then bounds-checked coalesced store
    __syncthreads();
    float* Cs = sm;                  // [128][GTN]
    #pragma unroll
    for (int i = 0; i < 2; i++)
        #pragma unroll
        for (int j = 0; j < 4; j++)
            wmma::store_matrix_sync(Cs + (wm * 32 + i * 16) * GTN + wn * 64 + j * 16,
                                    acc[i][j], GTN, wmma::mem_row_major);
    __syncthreads();

    for (int i = tid; i < GTM * GTN; i += 256) {
        int r = i >> 7;
        int c = i & 127;
        int n = n0 + c;
        if (n < VV) out[(size_t)(m0 + r) * VV + n] = Cs[r * GTN + c];
    }
}

// ---------------------------------------------------------------------------

#define RNN_SMEM  ((UU * HH + 2 * HH) * 4 + 2 * SS * 4)
#define GEMM_SMEM (2 * 128 * 132 * 4)

extern "C" void kernel_launch(void* const* d_in, const int* in_sizes, int n_in,
                              void* d_out, int out_size)
{
    const int*   users = (const int*)d_in[0];
    const int*   items = (const int*)d_in[1];
    const float* h0    = (const float*)d_in[2];
    const float* P_ru  = (const float*)d_in[3];
    const float* W_ru  = (const float*)d_in[4];
    const float* b_ru  = (const float*)d_in[5];
    const float* P_c   = (const float*)d_in[6];
    const float* W_c   = (const float*)d_in[7];
    const float* b_c   = (const float*)d_in[8];
    const float* ws    = (const float*)d_in[9];
    float* out = (float*)d_out;

    cudaFuncSetAttribute(rnn_kernel,  cudaFuncAttributeMaxDynamicSharedMemorySize, RNN_SMEM);
    cudaFuncSetAttribute(gemm_kernel, cudaFuncAttributeMaxDynamicSharedMemorySize, GEMM_SMEM);

    rnn_kernel<<<BB, 384, RNN_SMEM>>>(users, items, h0, P_ru, W_ru, b_ru, P_c, W_c, b_c);

    dim3 grid((VV + GTN - 1) / GTN, (BB * SS) / GTM);
    gemm_kernel<<<grid, 256, GEMM_SMEM>>>(ws, out);
}

// round 3
// speedup vs baseline: 1.8882x; 1.8882x over previous
#include <cuda_runtime.h>
#include <cstdint>

#define BB 32
#define SS 128
#define UU 256
#define HH 128
#define VV 30001
#define NT_N 235             // n tiles of 128 (235*128 = 30080 padded)
#define NT_M 32              // m tiles of 128

__device__ float g_outs[BB * SS * HH];      // RNN outputs [4096][128]
__device__ float g_wsT[NT_N * 128 * HH];    // ws transposed [30080][128], k-contiguous

// ---------------------------------------------------------------------------
__device__ __forceinline__ uint32_t smem_u32(const void* p) {
    uint32_t a;
    asm("{ .reg .u64 t; cvta.to.shared.u64 t, %1; cvt.u32.u64 %0, t; }" : "=r"(a) : "l"(p));
    return a;
}
#define CP_ASYNC16(s, g) \
    asm volatile("cp.async.cg.shared.global [%0], [%1], 16;" :: "r"(s), "l"(g) : "memory")
#define CP_COMMIT()  asm volatile("cp.async.commit_group;" ::: "memory")
#define CP_WAIT1()   asm volatile("cp.async.wait_group 1;" ::: "memory")
#define CP_WAIT0()   asm volatile("cp.async.wait_group 0;" ::: "memory")

__device__ __forceinline__ uint32_t cvt_tf32(float f) {
    uint32_t u;
    asm("cvt.rna.tf32.f32 %0, %1;" : "=r"(u) : "f"(f));
    return u;
}
__device__ __forceinline__ void mma_op(float* d, const uint32_t* a, uint32_t b0, uint32_t b1) {
    asm volatile("mma.sync.aligned.m16n8k8.row.col.f32.tf32.tf32.f32 "
                 "{%0,%1,%2,%3}, {%4,%5,%6,%7}, {%8,%9}, {%0,%1,%2,%3};"
                 : "+f"(d[0]), "+f"(d[1]), "+f"(d[2]), "+f"(d[3])
                 : "r"(a[0]), "r"(a[1]), "r"(a[2]), "r"(a[3]), "r"(b0), "r"(b1));
}

// ---------------------------------------------------------------------------
// ws transpose: ws[128][30001] -> wsT[30080][128] (padding zero-filled)
// ---------------------------------------------------------------------------
__global__ void transpose_ws(const float* __restrict__ ws, float* __restrict__ wsT) {
    __shared__ float t[32][33];
    int n0 = blockIdx.x * 32, k0 = blockIdx.y * 32;
    for (int i = threadIdx.y; i < 32; i += 8) {
        int n = n0 + threadIdx.x;
        t[i][threadIdx.x] = (n < VV) ? ws[(size_t)(k0 + i) * VV + n] : 0.f;
    }
    __syncthreads();
    for (int i = threadIdx.y; i < 32; i += 8)
        wsT[(size_t)(n0 + i) * HH + k0 + threadIdx.x] = t[threadIdx.x][i];
}

// ---------------------------------------------------------------------------
// RNN: one CTA per batch, 384 threads, state in smem, W columns in registers,
// next-step P_ru/P_c rows prefetched one iteration ahead.
// ---------------------------------------------------------------------------
__global__ __launch_bounds__(384, 1)
void rnn_kernel(const int* __restrict__ users, const int* __restrict__ items,
                const float* __restrict__ h0,
                const float* __restrict__ P_ru, const float* __restrict__ W_ru,
                const float* __restrict__ b_ru,
                const float* __restrict__ P_c, const float* __restrict__ W_c,
                const float* __restrict__ b_c)
{
    extern __shared__ float sm[];
    float* state_s = sm;
    float* rh_s    = sm + UU * HH;
    float* z_s     = rh_s + HH;
    int*   users_s = (int*)(z_s + HH);
    int*   items_s = users_s + SS;

    const int b   = blockIdx.x;
    const int tid = threadIdx.x;

    for (int t = tid; t < SS; t += blockDim.x) {
        users_s[t] = users[b * SS + t];
        items_s[t] = items[b * SS + t];
    }
    {
        const float4* src = (const float4*)(h0 + (size_t)b * UU * HH);
        float4* dst = (float4*)state_s;
        for (int i = tid; i < UU * HH / 4; i += blockDim.x) dst[i] = src[i];
    }

    float wreg[HH];
    float breg;
    if (tid < 2 * HH) {
        #pragma unroll
        for (int k = 0; k < HH; k++) wreg[k] = W_ru[k * (2 * HH) + tid];
        breg = b_ru[tid];
    } else {
        const int j = tid - 2 * HH;
        #pragma unroll
        for (int k = 0; k < HH; k++) wreg[k] = W_c[k * HH + j];
        breg = b_c[j];
    }
    __syncthreads();

    float pA;
    {
        int it0 = items_s[0];
        pA = (tid < 2 * HH) ? P_ru[(size_t)it0 * (2 * HH) + tid]
                            : P_c[(size_t)it0 * HH + (tid - 2 * HH)];
    }

    for (int t = 0; t < SS; t++) {
        const int u = users_s[t];
        const int itn = items_s[(t + 1) & (SS - 1)];
        float pN = (tid < 2 * HH) ? P_ru[(size_t)itn * (2 * HH) + tid]
                                  : P_c[(size_t)itn * HH + (tid - 2 * HH)];

        if (tid < 2 * HH) {
            const float* hs = state_s + u * HH;
            float a0 = 0.f, a1 = 0.f, a2 = 0.f, a3 = 0.f;
            #pragma unroll
            for (int k = 0; k < HH; k += 4) {
                float4 h4 = *(const float4*)(hs + k);
                a0 += h4.x * wreg[k];
                a1 += h4.y * wreg[k + 1];
                a2 += h4.z * wreg[k + 2];
                a3 += h4.w * wreg[k + 3];
            }
            float x = pA + breg + (a0 + a1) + (a2 + a3);
            float sgm = 1.f / (1.f + __expf(-x));
            if (tid < HH) rh_s[tid] = sgm * hs[tid];
            else          z_s[tid - HH] = sgm;
        }
        __syncthreads();

        if (tid >= 2 * HH) {
            const int j = tid - 2 * HH;
            float a0 = 0.f, a1 = 0.f, a2 = 0.f, a3 = 0.f;
            #pragma unroll
            for (int k = 0; k < HH; k += 4) {
                float4 r4 = *(const float4*)(rh_s + k);
                a0 += r4.x * wreg[k];
                a1 += r4.y * wreg[k + 1];
                a2 += r4.z * wreg[k + 2];
                a3 += r4.w * wreg[k + 3];
            }
            float x = pA + breg + (a0 + a1) + (a2 + a3);
            float c = tanhf(x);
            float h_old = state_s[u * HH + j];
            float z = z_s[j];
            float hn = z * h_old + (1.f - z) * c;
            state_s[u * HH + j] = hn;
            g_outs[((size_t)b * SS + t) * HH + j] = hn;
        }
        __syncthreads();
        pA = pN;
    }
}

// ---------------------------------------------------------------------------
// Persistent SIMT-tensor GEMM: out[4096,30001] = g_outs[4096,128] @ wsT^T
// 148 CTAs x 256 threads (8 warps, each owns 16 M-rows).
// A in registers across the whole n-run; B double-buffered via cp.async.
// mma.sync.m16n8k8 tf32, direct register->gmem epilogue.
// ---------------------------------------------------------------------------
#define LDB_F 132
#define BS_FLOATS (128 * LDB_F)
#define BS_BYTES  (BS_FLOATS * 4)         // 67584
#define GEMM_SMEM (2 * BS_BYTES)          // 135168
#define GRID_G 148

__device__ __forceinline__ void stage_B(uint32_t sbuf, int nt, int tid) {
    const float* src = g_wsT + (size_t)nt * (128 * HH);
    #pragma unroll
    for (int jj = 0; jj < 16; jj++) {
        int c = tid + jj * 256;           // 0..4095 chunks of 16B
        int n = c >> 5, k4 = c & 31;
        uint32_t dst = sbuf + (uint32_t)(n * LDB_F + k4 * 4) * 4;
        CP_ASYNC16(dst, src + n * HH + k4 * 4);
    }
}

__device__ __forceinline__ void load_a(uint32_t a[16][4], int mt, int w, int l) {
    const float* A0 = g_outs + (size_t)(mt * 128 + w * 16 + (l >> 2)) * HH;
    const float* A1 = A0 + 8 * HH;
    #pragma unroll
    for (int ks = 0; ks < 16; ks++) {
        int k0 = ks * 8 + (l & 3);
        a[ks][0] = cvt_tf32(A0[k0]);
        a[ks][1] = cvt_tf32(A1[k0]);
        a[ks][2] = cvt_tf32(A0[k0 + 4]);
        a[ks][3] = cvt_tf32(A1[k0 + 4]);
    }
}

__global__ __launch_bounds__(256, 1)
void gemm_kernel(float* __restrict__ out)
{
    extern __shared__ float smf[];
    const int tid = threadIdx.x;
    const int w = tid >> 5, l = tid & 31;
    const uint32_t sbase = smem_u32(smf);

    const int cta = blockIdx.x;
    // 7520 tiles = 148*50 + 120 -> first 120 CTAs take 51
    int t0  = cta * 50 + (cta < 120 ? cta : 120);
    int cnt = 50 + (cta < 120 ? 1 : 0);
    int mt = t0 / NT_N;
    int nt = t0 - mt * NT_N;

    stage_B(sbase, nt, tid);
    CP_COMMIT();

    uint32_t a[16][4];
    load_a(a, mt, w, l);

    for (int i = 0; i < cnt; i++) {
        const int j = i + 1;
        const bool have_next = (j < cnt);
        int mt_j = mt, nt_j = nt + 1;
        if (nt_j == NT_N) { nt_j = 0; mt_j++; }

        if (have_next) {
            stage_B(sbase + (uint32_t)(j & 1) * BS_BYTES, nt_j, tid);
            CP_COMMIT();
            CP_WAIT1();
        } else {
            CP_WAIT0();
        }
        __syncthreads();

        // ---- compute 128x128 tile ----
        float acc[16][4];
        #pragma unroll
        for (int nf = 0; nf < 16; nf++) {
            acc[nf][0] = 0.f; acc[nf][1] = 0.f; acc[nf][2] = 0.f; acc[nf][3] = 0.f;
        }
        const float* Bp = smf + (size_t)(i & 1) * BS_FLOATS + (l >> 2) * LDB_F + (l & 3);
        #pragma unroll
        for (int ks = 0; ks < 16; ks++) {
            uint32_t b0[16], b1[16];
            #pragma unroll
            for (int nf = 0; nf < 16; nf++) {
                b0[nf] = cvt_tf32(Bp[nf * (8 * LDB_F) + ks * 8]);
                b1[nf] = cvt_tf32(Bp[nf * (8 * LDB_F) + ks * 8 + 4]);
            }
            #pragma unroll
            for (int nf = 0; nf < 16; nf++)
                mma_op(acc[nf], a[ks], b0[nf], b1[nf]);
        }

        // ---- epilogue: registers -> gmem ----
        {
            size_t r0 = (size_t)(mt * 128 + w * 16 + (l >> 2)) * VV;
            size_t r1 = r0 + (size_t)8 * VV;
            int colb = nt * 128 + (l & 3) * 2;
            if (nt < NT_N - 1) {
                #pragma unroll
                for (int nf = 0; nf < 16; nf++) {
                    int c = colb + nf * 8;
                    out[r0 + c]     = acc[nf][0];
                    out[r0 + c + 1] = acc[nf][1];
                    out[r1 + c]     = acc[nf][2];
                    out[r1 + c + 1] = acc[nf][3];
                }
            } else {
                #pragma unroll
                for (int nf = 0; nf < 16; nf++) {
                    int c = colb + nf * 8;
                    if (c < VV)     { out[r0 + c]     = acc[nf][0]; out[r1 + c]     = acc[nf][2]; }
                    if (c + 1 < VV) { out[r0 + c + 1] = acc[nf][1]; out[r1 + c + 1] = acc[nf][3]; }
                }
            }
        }
        __syncthreads();

        if (have_next && mt_j != mt) load_a(a, mt_j, w, l);
        mt = mt_j; nt = nt_j;
    }
}

// ---------------------------------------------------------------------------
#define RNN_SMEM ((UU * HH + 2 * HH) * 4 + 2 * SS * 4)

extern "C" void kernel_launch(void* const* d_in, const int* in_sizes, int n_in,
                              void* d_out, int out_size)
{
    const int*   users = (const int*)d_in[0];
    const int*   items = (const int*)d_in[1];
    const float* h0    = (const float*)d_in[2];
    const float* P_ru  = (const float*)d_in[3];
    const float* W_ru  = (const float*)d_in[4];
    const float* b_ru  = (const float*)d_in[5];
    const float* P_c   = (const float*)d_in[6];
    const float* W_c   = (const float*)d_in[7];
    const float* b_c   = (const float*)d_in[8];
    const float* ws    = (const float*)d_in[9];
    float* out = (float*)d_out;

    static int attr_done = 0;
    if (!attr_done) {
        cudaFuncSetAttribute(rnn_kernel,  cudaFuncAttributeMaxDynamicSharedMemorySize, RNN_SMEM);
        cudaFuncSetAttribute(gemm_kernel, cudaFuncAttributeMaxDynamicSharedMemorySize, GEMM_SMEM);
        attr_done = 1;
    }

    float* wsT;
    cudaGetSymbolAddress((void**)&wsT, g_wsT);

    transpose_ws<<<dim3(940, 4), dim3(32, 8)>>>(ws, wsT);
    rnn_kernel<<<BB, 384, RNN_SMEM>>>(users, items, h0, P_ru, W_ru, b_ru, P_c, W_c, b_c);
    gemm_kernel<<<GRID_G, 256, GEMM_SMEM>>>(out);
}